// round 8
// baseline (speedup 1.0000x reference)
#include <cuda_runtime.h>
#include <cstdint>

#define B_  2
#define N_  4
#define D_  48
#define H_  28
#define W_  60
#define C_  64
#define NX_ 192
#define NY_ 192
// NZ = 1

// Scratch accumulator in C-contiguous layout (B, NY, NX, C) so vector reds work.
// Zero-initialized at module load; transpose_kernel restores it to zero every
// launch, so the zero-at-entry invariant holds across graph replays.
__device__ float g_scratch[B_ * NY_ * NX_ * C_];
// Per-(b,n): 9 floats of combine = R @ inv(K), then 3 floats of trans.
__device__ float g_geo[B_ * N_ * 12];

// ---------------------------------------------------------------------------
// Setup: 8 (b,n) pairs -> combine rows + trans. Mimics float32 reference math.
// ---------------------------------------------------------------------------
__global__ void setup_kernel(const float* __restrict__ intr,
                             const float* __restrict__ pose) {
    int i = threadIdx.x;
    if (i >= B_ * N_) return;
    const float* K = intr + i * 9;
    const float* P = pose + i * 16;

    float a = K[0], bb = K[1], c = K[2];
    float d = K[3], e  = K[4], f = K[5];
    float g = K[6], h  = K[7], ii = K[8];

    float A0 = e * ii - f * h;
    float A1 = f * g  - d * ii;
    float A2 = d * h  - e * g;
    float det = a * A0 + bb * A1 + c * A2;

    float inv[9];
    inv[0] = A0 / det;             inv[1] = (c * h - bb * ii) / det; inv[2] = (bb * f - c * e) / det;
    inv[3] = A1 / det;             inv[4] = (a * ii - c * g) / det;  inv[5] = (c * d - a * f) / det;
    inv[6] = A2 / det;             inv[7] = (bb * g - a * h) / det;  inv[8] = (a * e - bb * d) / det;

    for (int r = 0; r < 3; r++) {
        for (int j = 0; j < 3; j++) {
            float s = P[r * 4 + 0] * inv[0 * 3 + j];
            s = fmaf(P[r * 4 + 1], inv[1 * 3 + j], s);
            s = fmaf(P[r * 4 + 2], inv[2 * 3 + j], s);
            g_geo[i * 12 + r * 3 + j] = s;
        }
        g_geo[i * 12 + 9 + r] = P[r * 4 + 3];
    }
}

// Vectorized fire-and-forget reduction (sm_90+): one 16B red per sub-lane.
__device__ __forceinline__ void red_add_v4(float* addr, float4 v) {
    asm volatile("red.global.add.v4.f32 [%0], {%1, %2, %3, %4};"
                 :: "l"(addr), "f"(v.x), "f"(v.y), "f"(v.z), "f"(v.w)
                 : "memory");
}

__device__ __forceinline__ void cp_async16(void* smem_dst, const void* gsrc) {
    uint32_t daddr = (uint32_t)__cvta_generic_to_shared(smem_dst);
    asm volatile("cp.async.cg.shared.global [%0], [%1], 16;"
                 :: "r"(daddr), "l"(gsrc));
}

// ---------------------------------------------------------------------------
// Scatter, cp.async-staged. Block = (b, d, h, n-pair): owns 2 view-slabs of
// x[b,n,d,h,:,:] (60 w x 64 c = 15,360B each).
//   1) threads t<120 compute flat-or-neg1 for (2 views x 60 w) — exact
//      reference fp32 chain (identical to the R5-passing kernel).
//   2) data-driven ballot: slabs with any kept point are bulk-copied to SMEM
//      via cp.async (deep async pipeline -> DRAM-read roofline, no LDG stall).
//   3) 16 half-warp groups (2 views x 8 contiguous w-windows); sub-lane owns
//      4 channels. Register-merge consecutive w hitting the same voxel
//      (data-driven flat==cur check), flush via red.global.add.v4.
// Non-kept blocks (e.g. frustum-culled depths) exit after step 1.
// ---------------------------------------------------------------------------
__global__ void __launch_bounds__(256)
scatter_kernel(const float* __restrict__ x) {
    __shared__ float s_x[2][W_ * C_];     // 2 x 15,360B
    __shared__ int   s_flat[2 * W_];
    __shared__ int   s_any[2];

    int blk   = blockIdx.x;               // ((b*D + d)*H + h)*2 + npair
    int npair = blk & 1;
    int tmp   = blk >> 1;
    int h = tmp % H_;  tmp /= H_;
    int d = tmp % D_;
    int b = tmp / D_;
    int t = threadIdx.x;

    if (t < 2) s_any[t] = 0;
    __syncthreads();

    if (t < 2 * W_) {
        int nl = t / W_;
        int w  = t % W_;
        int n  = npair * 2 + nl;

        float df = 2.0f + (float)d;                 // ds = arange(2,50,1)
        float u  = (float)w * (479.0f / 59.0f);     // linspace(0, 479, 60)
        float v  = (float)h * (223.0f / 27.0f);     // linspace(0, 223, 28)
        float p0 = u * df, p1 = v * df, p2 = df;

        const float* G = g_geo + (b * N_ + n) * 12;
        float dx = G[0] * p0; dx = fmaf(G[1], p1, dx); dx = fmaf(G[2], p2, dx);
        float dy = G[3] * p0; dy = fmaf(G[4], p1, dy); dy = fmaf(G[5], p2, dy);
        float dz = G[6] * p0; dz = fmaf(G[7], p1, dz); dz = fmaf(G[8], p2, dz);
        float gxf = dx + G[9];
        float gyf = dy + G[10];
        float gzf = dz + G[11];

        // Truncation toward zero == jnp astype(int32); (-0.5 -> 0 is KEPT in both)
        int gx = (int)(gxf * 4.0f + 96.0f);
        int gy = (int)(gyf * 4.0f + 96.0f);
        int gz = (int)__fdiv_rn(gzf + 10.0f, 20.0f);

        int flat = -1;
        if (gx >= 0 && gx < NX_ && gy >= 0 && gy < NY_ && gz >= 0 && gz < 1)
            flat = ((b /*NZ=1*/ + gz) * NY_ + gy) * NX_ + gx;
        s_flat[t] = flat;
        if (flat >= 0) s_any[nl] = 1;     // benign race (all writers store 1)
    }
    __syncthreads();

    if (!s_any[0] && !s_any[1]) return;   // uniform: whole block culled

    // Bulk-copy kept slabs (uniform branches: s_any is smem-shared).
    #pragma unroll
    for (int nl = 0; nl < 2; nl++) {
        if (!s_any[nl]) continue;
        int n = npair * 2 + nl;
        const float4* src = (const float4*)(x
            + ((((size_t)b * N_ + n) * D_ + d) * H_ + h) * (size_t)(W_ * C_));
        float4* dst = (float4*)s_x[nl];
        for (int i = t; i < (W_ * C_) / 4; i += 256)
            cp_async16(dst + i, src + i);
    }
    asm volatile("cp.async.commit_group;\ncp.async.wait_group 0;" ::: "memory");
    __syncthreads();

    // Process: group g = (view nl, w-window wq); sub-lane = channel quad.
    int g   = t >> 4;
    int sub = t & 15;
    int nl  = g >> 3;                     // 0..1
    int wq  = g & 7;                      // 0..7
    int w0  = wq * 8;
    int w1  = (w0 + 8 < W_) ? (w0 + 8) : W_;   // windows 8,8,...,8,4

    if (s_any[nl]) {
        int    cur = -1;
        float4 acc = make_float4(0.f, 0.f, 0.f, 0.f);
        for (int w = w0; w < w1; w++) {
            int f = s_flat[nl * W_ + w];
            if (f >= 0) {
                float4 xv = *(const float4*)&s_x[nl][w * C_ + sub * 4];
                if (f == cur) {
                    acc.x += xv.x; acc.y += xv.y; acc.z += xv.z; acc.w += xv.w;
                } else {
                    if (cur >= 0)
                        red_add_v4(g_scratch + (size_t)cur * C_ + sub * 4, acc);
                    cur = f; acc = xv;
                }
            }
        }
        if (cur >= 0)
            red_add_v4(g_scratch + (size_t)cur * C_ + sub * 4, acc);
    }
}

// ---------------------------------------------------------------------------
// Transpose scratch (B,NY,NX,C) -> out (B, C, NY, NX), and restore scratch to
// zero for the next replay (replaces the standalone zero kernel).
// float4 reads, float4 zero-writeback, float4 coalesced out-stores
// (4 x 128B segments per warp instruction; LDS pattern is bank-conflict-free).
// ---------------------------------------------------------------------------
__global__ void transpose_kernel(float* __restrict__ out) {
    __shared__ float s[32][C_ + 1];
    int tile = blockIdx.x;                    // B * NY * (NX/32) = 2304
    int xt = tile % (NX_ / 32);
    int y  = (tile / (NX_ / 32)) % NY_;
    int b  = tile / ((NX_ / 32) * NY_);

    float4* src = (float4*)(g_scratch
        + (((size_t)b * NY_ + y) * NX_ + (size_t)xt * 32) * C_);

    int t = threadIdx.x;                      // 256 threads; 512 float4 per tile
    #pragma unroll
    for (int k = 0; k < 2; k++) {
        int i = t + k * 256;
        float4 val = src[i];
        src[i] = make_float4(0.f, 0.f, 0.f, 0.f);   // self-restore scratch
        int xx = i >> 4;                      // / (C_/4)
        int cc = (i & 15) << 2;
        s[xx][cc + 0] = val.x; s[xx][cc + 1] = val.y;
        s[xx][cc + 2] = val.z; s[xx][cc + 3] = val.w;
    }
    __syncthreads();

    size_t obase = ((size_t)b * C_) * (NY_ * NX_) + (size_t)y * NX_
                 + (size_t)xt * 32;
    #pragma unroll
    for (int k = 0; k < 2; k++) {
        int p  = t + k * 256;                 // 512 (c, x-quad) pairs
        int x4 = (p & 7) * 4;                 // octet of lanes -> 128B run in x
        int c  = p >> 3;
        float4 v = make_float4(s[x4 + 0][c], s[x4 + 1][c],
                               s[x4 + 2][c], s[x4 + 3][c]);
        *(float4*)(out + obase + (size_t)c * (NY_ * NX_) + x4) = v;
    }
}

// ---------------------------------------------------------------------------
extern "C" void kernel_launch(void* const* d_in, const int* in_sizes, int n_in,
                              void* d_out, int out_size) {
    // Resolve inputs by element count (robust to metadata ordering):
    //   x: B*N*D*H*W*C = 41,287,680   pose: B*N*16 = 128   intrinsics: B*N*9 = 72
    const float* x    = nullptr;
    const float* intr = nullptr;
    const float* pose = nullptr;
    for (int i = 0; i < n_in; i++) {
        if (in_sizes[i] == B_ * N_ * 16)      pose = (const float*)d_in[i];
        else if (in_sizes[i] == B_ * N_ * 9)  intr = (const float*)d_in[i];
        else                                  x    = (const float*)d_in[i];
    }
    float* out = (float*)d_out;

    setup_kernel<<<1, 32>>>(intr, pose);

    const int nblocks = B_ * D_ * H_ * 2;     // (b, d, h, n-pair) = 5376
    scatter_kernel<<<nblocks, 256>>>(x);

    transpose_kernel<<<B_ * NY_ * (NX_ / 32), 256>>>(out);
}